// round 9
// baseline (speedup 1.0000x reference)
#include <cuda_runtime.h>
#include <math.h>

#define BB 8
#define RR 4096
#define CC 1024
#define NROW (BB * RR)
#define GRID 148          // <= SM count on B300(148)/GB300(152): all CTAs co-resident
#define RPC 28            // rows per CTA per batch: 147*28 = 4116 >= 4096 (CTA 147 owns 0)
#define NSTEP 10          // 8 batches + 2 pipeline drain steps

// Scratch + barrier state (no allocations allowed).
__device__ float d_mags[NROW];
__device__ float d_thr[BB];
__device__ unsigned g_count = 0;
__device__ unsigned g_gen = 0;

// Branch-free two-sum accumulate: s += t with running compensation c.
__device__ __forceinline__ void twosum_acc(float& s, float& c, float t) {
    float y  = s + t;
    float bp = y - s;
    c += (s - (y - bp)) + (t - bp);
    s = y;
}
__device__ __forceinline__ void twosum_merge(float& s, float& c, float so, float co) {
    float S  = s + so;
    float bp = S - s;
    float e  = (s - (S - bp)) + (so - bp);
    c = c + co + e;
    s = S;
}

// Grid-wide barrier. Safe because all GRID CTAs are co-resident (grid <= #SMs,
// trivial per-CTA resources). Generation-based, wrap-safe, graph-replay-safe
// (caller supplies absolute target = entry generation + barrier index).
__device__ __forceinline__ void grid_barrier(unsigned target) {
    __syncthreads();
    if (threadIdx.x == 0) {
        __threadfence();
        unsigned old = atomicAdd(&g_count, 1);
        if (old == GRID - 1) {
            g_count = 0;          // reaches L2 before the releasing gen bump
            __threadfence();
            atomicAdd(&g_gen, 1);
        } else {
            while ((int)(*(volatile unsigned*)&g_gen) - (int)target < 0)
                __nanosleep(64);
            __threadfence();
        }
    }
    __syncthreads();
}

// ---------------------------------------------------------------------------
// One persistent kernel. Step s (0..9), grid barrier between steps:
//   A: CTAs with rows compute compensated-fp32 norms of batch s   (s < 8)
//   T: CTA 147 (owns no rows) computes k + radix-select thr(s-1)  (1<=s<=8)
//   B: all CTAs emit output for batch s-2 (kept rows: L2-hit copy; dropped:
//      zero stores). __ldcs/__stcs keep the streams from evicting the
//      batches still pending reuse.
// ---------------------------------------------------------------------------
__global__ void __launch_bounds__(256, 1)
fused_kernel(const float4* __restrict__ w, float4* __restrict__ out,
             const float* __restrict__ logits,
             const float* __restrict__ score_w,
             const float* __restrict__ score_b) {
    const int cta  = blockIdx.x;
    const int tid  = threadIdx.x;
    const int warp = tid >> 5;
    const int lane = tid & 31;

    __shared__ float   sm_mags[3][RPC];   // ring: batch b lives in slot b%3
    __shared__ double  sdot[256];
    __shared__ unsigned hist[256], sufA[256], sufB[256];
    __shared__ unsigned sh_prefix;
    __shared__ int      sh_k;

    unsigned gen0 = 0;
    if (tid == 0) gen0 = *(volatile unsigned*)&g_gen;  // stable: no barrier can
                                                       // complete before all arrive
    const int row0  = cta * RPC;
    const int nrows = max(0, min(RR, row0 + RPC) - row0);

    for (int s = 0; s < NSTEP; s++) {
        // ---- Phase A: norms of batch s ----
        if (s < BB) {
            for (int lr = warp; lr < nrows; lr += 8) {
                const int grow = s * RR + row0 + lr;
                const float4* rp = w + (size_t)grow * 256;
                float s0 = 0.f, c0 = 0.f, s1 = 0.f, c1 = 0.f;
                float s2 = 0.f, c2 = 0.f, s3 = 0.f, c3 = 0.f;
#pragma unroll
                for (int i = 0; i < 8; i++) {
                    float4 v = rp[lane + i * 32];   // default ld: stays in L2 for B
                    twosum_acc(s0, c0, v.x * v.x);
                    twosum_acc(s1, c1, v.y * v.y);
                    twosum_acc(s2, c2, v.z * v.z);
                    twosum_acc(s3, c3, v.w * v.w);
                }
                twosum_merge(s0, c0, s1, c1);
                twosum_merge(s2, c2, s3, c3);
                twosum_merge(s0, c0, s2, c2);
#pragma unroll
                for (int off = 16; off > 0; off >>= 1) {
                    float so = __shfl_down_sync(0xffffffffu, s0, off);
                    float co = __shfl_down_sync(0xffffffffu, c0, off);
                    twosum_merge(s0, c0, so, co);
                }
                if (lane == 0) {
                    float m = sqrtf(s0 + c0);
                    sm_mags[s % 3][lr] = m;
                    d_mags[grow] = m;             // for the thr CTA
                }
            }
        }

        // ---- Phase T: threshold for batch s-1 (CTA 147, which owns no rows) ----
        if (cta == GRID - 1 && s >= 1 && s <= BB) {
            const int b = s - 1;
            // (a) fp64 score dot -> fp32 sigmoid -> k (matches jax boundary)
            double acc = 0.0;
            for (int j = tid; j < CC; j += 256)
                acc += (double)logits[b * CC + j] * (double)score_w[j];
            sdot[tid] = acc;
            __syncthreads();
#pragma unroll
            for (int st = 128; st > 0; st >>= 1) {
                if (tid < st) sdot[tid] += sdot[tid + st];
                __syncthreads();
            }
            if (tid == 0) {
                float sc = (float)sdot[0] + score_b[0];
                float kf = 1.0f / (1.0f + expf(-sc));
                int k = (int)(kf * (float)RR);
                if (k < 1) k = 1;
                if (k > RR) k = RR;
                sh_k = k;
            }
            __syncthreads();

            // (b) radix select k-th largest magnitude (monotone float bits)
            unsigned prefix = 0;
            int k = sh_k;
            const float* mags = d_mags + b * RR;
            for (int shift = 24; shift >= 0; shift -= 8) {
                hist[tid] = 0;
                __syncthreads();
                unsigned hi_mask = (shift == 24) ? 0u : (0xFFFFFFFFu << (shift + 8));
#pragma unroll
                for (int i = 0; i < RR / 256; i++) {
                    unsigned key = __float_as_uint(__ldcg(&mags[tid + i * 256]));
                    unsigned digit = ((key & hi_mask) == (prefix & hi_mask))
                                         ? ((key >> shift) & 0xFFu) : 256u;
                    unsigned peers = __match_any_sync(0xffffffffu, digit);
                    int leader = __ffs(peers) - 1;
                    if (lane == leader && digit < 256u)
                        atomicAdd(&hist[digit], (unsigned)__popc(peers));
                }
                __syncthreads();
                // parallel suffix sum over 256 bins
                sufA[tid] = hist[tid];
                __syncthreads();
                unsigned* src = sufA; unsigned* dst = sufB;
#pragma unroll
                for (int off = 1; off < 256; off <<= 1) {
                    unsigned add = (tid + off < 256) ? src[tid + off] : 0u;
                    dst[tid] = src[tid] + add;
                    __syncthreads();
                    unsigned* t = src; src = dst; dst = t;
                }
                unsigned mycum  = src[tid];
                unsigned nextcum = (tid == 255) ? 0u : src[tid + 1];
                if (mycum >= (unsigned)k && nextcum < (unsigned)k) {
                    sh_prefix = prefix | ((unsigned)tid << shift);
                    sh_k = k - (int)nextcum;
                }
                __syncthreads();
                prefix = sh_prefix;
                k = sh_k;
                __syncthreads();
            }
            if (tid == 0) d_thr[b] = __uint_as_float(prefix);
        }

        // ---- Phase B: output batch s-2 ----
        if (s >= 2) {
            const int b = s - 2;
            const float thr = __ldcg(&d_thr[b]);   // written by CTA147 last step
            const float4 z = make_float4(0.f, 0.f, 0.f, 0.f);
            for (int lr = warp; lr < nrows; lr += 8) {
                const int grow = b * RR + row0 + lr;
                float4* op = out + (size_t)grow * 256;
                if (sm_mags[b % 3][lr] >= thr) {
                    const float4* rp = w + (size_t)grow * 256;
#pragma unroll
                    for (int i = 0; i < 8; i++) {
                        float4 v = __ldcs(rp + lane + i * 32);  // L2 hit, evict-first
                        __stcs(op + lane + i * 32, v);
                    }
                } else {
#pragma unroll
                    for (int i = 0; i < 8; i++)
                        __stcs(op + lane + i * 32, z);
                }
            }
        }

        if (s < NSTEP - 1) grid_barrier(gen0 + (unsigned)s + 1u);
    }
}

// ---------------------------------------------------------------------------
extern "C" void kernel_launch(void* const* d_in, const int* in_sizes, int n_in,
                              void* d_out, int out_size) {
    const float* w       = (const float*)d_in[0];  // [8,4096,1024] f32
    const float* logits  = (const float*)d_in[1];  // [8,1024] f32
    const float* score_w = (const float*)d_in[2];  // [1024,1] f32
    const float* score_b = (const float*)d_in[3];  // [1] f32

    (void)in_sizes; (void)n_in; (void)out_size;

    fused_kernel<<<GRID, 256>>>((const float4*)w, (float4*)d_out,
                                logits, score_w, score_b);
}

// round 10
// speedup vs baseline: 1.9886x; 1.9886x over previous
#include <cuda_runtime.h>
#include <math.h>

#define BB 8
#define RR 4096
#define CC 1024
#define NROW (BB * RR)

// Scratch (no allocations allowed): per-row magnitudes + per-batch thresholds.
__device__ float d_mags[NROW];
__device__ float d_thr[BB];

// Branch-free two-sum accumulate: s += t with running compensation c.
__device__ __forceinline__ void twosum_acc(float& s, float& c, float t) {
    float y  = s + t;
    float bp = y - s;
    c += (s - (y - bp)) + (t - bp);
    s = y;
}
__device__ __forceinline__ void twosum_merge(float& s, float& c, float so, float co) {
    float S  = s + so;
    float bp = S - s;
    float e  = (s - (S - bp)) + (so - bp);
    c = c + co + e;
    s = S;
}

// ---------------------------------------------------------------------------
// Kernel 1: fused copy + per-row L2 magnitudes. One warp per row (256 float4;
// 8 float4 per lane, coalesced). MLP-restructured: all 8 loads are issued
// back-to-back into registers (8 x 512B independent in flight per warp),
// then all stores, then the compensated accumulation — so DRAM latency is
// covered by load-batching instead of being serialized behind FMA chains.
// Compensated fp32 (4 independent pairs + compensated shuffle tree):
// ~2^-45 relative error, far below the ~1.4e-5 gap between adjacent order
// statistics, so the top-k boundary matches the jax fp32 reference exactly.
// ---------------------------------------------------------------------------
__global__ void __launch_bounds__(256)
copy_norms_kernel(const float4* __restrict__ w, float4* __restrict__ out) {
    int gwarp = (blockIdx.x * blockDim.x + threadIdx.x) >> 5;
    int lane = threadIdx.x & 31;

    const float4* row = w + (size_t)gwarp * 256;
    float4* orow = out + (size_t)gwarp * 256;

    // Front-batched loads: 8 independent 128-bit loads per lane.
    float4 v[8];
#pragma unroll
    for (int i = 0; i < 8; i++)
        v[i] = row[lane + i * 32];

    // Streaming copy (stores are issue-cost only; overlap with compute below).
#pragma unroll
    for (int i = 0; i < 8; i++)
        orow[lane + i * 32] = v[i];

    float s0 = 0.f, c0 = 0.f, s1 = 0.f, c1 = 0.f;
    float s2 = 0.f, c2 = 0.f, s3 = 0.f, c3 = 0.f;
#pragma unroll
    for (int i = 0; i < 8; i++) {
        twosum_acc(s0, c0, v[i].x * v[i].x);
        twosum_acc(s1, c1, v[i].y * v[i].y);
        twosum_acc(s2, c2, v[i].z * v[i].z);
        twosum_acc(s3, c3, v[i].w * v[i].w);
    }
    twosum_merge(s0, c0, s1, c1);
    twosum_merge(s2, c2, s3, c3);
    twosum_merge(s0, c0, s2, c2);

    // Compensated cross-lane reduction.
#pragma unroll
    for (int off = 16; off > 0; off >>= 1) {
        float so = __shfl_down_sync(0xffffffffu, s0, off);
        float co = __shfl_down_sync(0xffffffffu, c0, off);
        twosum_merge(s0, c0, so, co);
    }
    if (lane == 0) d_mags[gwarp] = sqrtf(s0 + c0);
}

// ---------------------------------------------------------------------------
// Kernel 2: one block per batch (256 threads).
//   (a) fp64 dot(logits[b], score_w) + score_b -> fp32 sigmoid -> k
//   (b) radix-select k-th largest magnitude:
//       - __match_any_sync warp-aggregated smem atomics (norms concentrate
//         near 32.0 -> early passes dump ~all 4096 values into ONE bin)
//       - parallel suffix-sum over the 256 bins (8 double-buffered steps)
// ---------------------------------------------------------------------------
__global__ void thr_kernel(const float* __restrict__ logits,
                           const float* __restrict__ score_w,
                           const float* __restrict__ score_b) {
    const int b = blockIdx.x;
    const int tid = threadIdx.x;  // 256 threads
    const int lane = tid & 31;

    __shared__ double sdot[256];
    __shared__ unsigned hist[256];
    __shared__ unsigned sufA[256];
    __shared__ unsigned sufB[256];
    __shared__ unsigned sh_prefix;
    __shared__ int sh_k;

    // --- (a) score -> k ---
    double acc = 0.0;
    for (int j = tid; j < CC; j += 256)
        acc += (double)logits[b * CC + j] * (double)score_w[j];
    sdot[tid] = acc;
    __syncthreads();
#pragma unroll
    for (int s2 = 128; s2 > 0; s2 >>= 1) {
        if (tid < s2) sdot[tid] += sdot[tid + s2];
        __syncthreads();
    }
    if (tid == 0) {
        float s = (float)sdot[0] + score_b[0];
        float kf = 1.0f / (1.0f + expf(-s));           // fp32 sigmoid, like ref
        int k = (int)(kf * (float)RR);                  // fp32 mul + trunc, like ref
        if (k < 1) k = 1;
        if (k > RR) k = RR;
        sh_k = k;
    }
    __syncthreads();

    // --- (b) radix select k-th largest among d_mags[b*RR .. +RR) ---
    unsigned prefix = 0;
    int k = sh_k;
    const float* mags = d_mags + b * RR;

    for (int shift = 24; shift >= 0; shift -= 8) {
        hist[tid] = 0;
        __syncthreads();

        unsigned hi_mask = (shift == 24) ? 0u : (0xFFFFFFFFu << (shift + 8));
#pragma unroll
        for (int i = 0; i < RR / 256; i++) {           // 16 values per thread
            unsigned key = __float_as_uint(mags[tid + i * 256]);
            unsigned digit = ((key & hi_mask) == (prefix & hi_mask))
                                 ? ((key >> shift) & 0xFFu) : 256u;
            unsigned peers = __match_any_sync(0xffffffffu, digit);
            int leader = __ffs(peers) - 1;
            if (lane == leader && digit < 256u)
                atomicAdd(&hist[digit], (unsigned)__popc(peers));
        }
        __syncthreads();

        // Parallel suffix sum: suf[d] = sum_{j >= d} hist[j]
        sufA[tid] = hist[tid];
        __syncthreads();
        unsigned* src = sufA;
        unsigned* dst = sufB;
#pragma unroll
        for (int off = 1; off < 256; off <<= 1) {
            unsigned add = (tid + off < 256) ? src[tid + off] : 0u;
            dst[tid] = src[tid] + add;
            __syncthreads();
            unsigned* t = src; src = dst; dst = t;
        }
        unsigned mycum = src[tid];
        unsigned nextcum = (tid == 255) ? 0u : src[tid + 1];
        if (mycum >= (unsigned)k && nextcum < (unsigned)k) {
            sh_prefix = prefix | ((unsigned)tid << shift);
            sh_k = k - (int)nextcum;
        }
        __syncthreads();
        prefix = sh_prefix;
        k = sh_k;
        __syncthreads();
    }

    if (tid == 0) d_thr[b] = __uint_as_float(prefix);
}

// ---------------------------------------------------------------------------
// Kernel 3: write-only zeroing of dropped rows. One warp per row; kept rows
// exit immediately (no traffic). Dropped rows: 256 float4 zero stores
// (full sectors, no write-allocate reads). Traffic ~= drop_fraction * 134MB.
// ---------------------------------------------------------------------------
__global__ void __launch_bounds__(256)
zero_kernel(float4* __restrict__ out) {
    int gwarp = (blockIdx.x * blockDim.x + threadIdx.x) >> 5;
    int lane = threadIdx.x & 31;
    int b = gwarp >> 12;                               // 4096 rows per batch

    if (__ldcg(&d_mags[gwarp]) >= __ldcg(&d_thr[b])) return;  // kept: already final

    float4* orow = out + (size_t)gwarp * 256;
    const float4 z = make_float4(0.f, 0.f, 0.f, 0.f);
#pragma unroll
    for (int i = 0; i < 8; i++)
        __stcg(orow + lane + i * 32, z);
}

// ---------------------------------------------------------------------------
extern "C" void kernel_launch(void* const* d_in, const int* in_sizes, int n_in,
                              void* d_out, int out_size) {
    const float* w       = (const float*)d_in[0];  // [8,4096,1024] f32
    const float* logits  = (const float*)d_in[1];  // [8,1024] f32
    const float* score_w = (const float*)d_in[2];  // [1024,1] f32
    const float* score_b = (const float*)d_in[3];  // [1] f32

    (void)in_sizes; (void)n_in; (void)out_size;

    // 32768 rows, 1 warp per row -> 4096 blocks of 256 threads
    copy_norms_kernel<<<4096, 256>>>((const float4*)w, (float4*)d_out);
    // one block per batch
    thr_kernel<<<BB, 256>>>(logits, score_w, score_b);
    // zero the dropped rows only
    zero_kernel<<<4096, 256>>>((float4*)d_out);
}

// round 11
// speedup vs baseline: 2.1125x; 1.0623x over previous
#include <cuda_runtime.h>
#include <math.h>

#define BB 8
#define RR 4096
#define CC 1024
#define NROW (BB * RR)

// Scratch (no allocations allowed).
__device__ float d_mags[NROW];
__device__ float d_thr[BB];
__device__ unsigned d_cnt[BB];   // zero-init at load; self-reset each run

// Branch-free two-sum accumulate: s += t with running compensation c.
__device__ __forceinline__ void twosum_acc(float& s, float& c, float t) {
    float y  = s + t;
    float bp = y - s;
    c += (s - (y - bp)) + (t - bp);
    s = y;
}
__device__ __forceinline__ void twosum_merge(float& s, float& c, float so, float co) {
    float S  = s + so;
    float bp = S - s;
    float e  = (s - (S - bp)) + (so - bp);
    c = c + co + e;
    s = S;
}

// ---------------------------------------------------------------------------
// Kernel 1: fused copy + per-row L2 norms + overlapped per-batch threshold.
//  - One warp per row (256 float4), coalesced copy W -> out; compensated fp32
//    norm (error ~2^-45, far below the ~1.4e-5 gap between adjacent order
//    statistics -> top-k boundary matches the jax fp32 reference exactly).
//  - 512 blocks per batch. The LAST block of each batch (atomic counter) also
//    computes that batch's k (fp64 score dot -> fp32 sigmoid, like ref) and
//    the k-th largest magnitude via radix select. For batches 0..6 this work
//    overlaps the remaining copy traffic of later batches entirely.
// ---------------------------------------------------------------------------
__global__ void __launch_bounds__(256)
copy_norms_thr_kernel(const float4* __restrict__ w, float4* __restrict__ out,
                      const float* __restrict__ logits,
                      const float* __restrict__ score_w,
                      const float* __restrict__ score_b) {
    const int tid  = threadIdx.x;
    const int lane = tid & 31;
    const int gwarp = (blockIdx.x << 3) + (tid >> 5);   // 8 rows per block

    __shared__ double   sdot[256];
    __shared__ unsigned hist[256], sufA[256], sufB[256];
    __shared__ unsigned sh_prefix, sh_done;
    __shared__ int      sh_k;

    // ---- copy + norm (hot path) ----
    {
        const float4* row = w + (size_t)gwarp * 256;
        float4* orow = out + (size_t)gwarp * 256;

        float s0 = 0.f, c0 = 0.f, s1 = 0.f, c1 = 0.f;
        float s2 = 0.f, c2 = 0.f, s3 = 0.f, c3 = 0.f;
#pragma unroll
        for (int i = 0; i < 8; i++) {
            float4 v = row[lane + i * 32];
            orow[lane + i * 32] = v;                    // streaming copy
            twosum_acc(s0, c0, v.x * v.x);
            twosum_acc(s1, c1, v.y * v.y);
            twosum_acc(s2, c2, v.z * v.z);
            twosum_acc(s3, c3, v.w * v.w);
        }
        twosum_merge(s0, c0, s1, c1);
        twosum_merge(s2, c2, s3, c3);
        twosum_merge(s0, c0, s2, c2);
#pragma unroll
        for (int off = 16; off > 0; off >>= 1) {
            float so = __shfl_down_sync(0xffffffffu, s0, off);
            float co = __shfl_down_sync(0xffffffffu, c0, off);
            twosum_merge(s0, c0, so, co);
        }
        if (lane == 0) d_mags[gwarp] = sqrtf(s0 + c0);
    }

    // ---- last-block-per-batch threshold (cold path, overlapped) ----
    const int b = blockIdx.x >> 9;                      // 512 blocks per batch
    __syncthreads();                                    // all 8 d_mags written
    if (tid == 0) {
        __threadfence();                                // publish d_mags to L2
        sh_done = atomicAdd(&d_cnt[b], 1u);
    }
    __syncthreads();
    if (sh_done != 511u) return;                        // not the last block

    // (a) fp64 score dot -> fp32 sigmoid -> k  (matches jax boundary)
    double acc = 0.0;
    for (int j = tid; j < CC; j += 256)
        acc += (double)logits[b * CC + j] * (double)score_w[j];
    sdot[tid] = acc;
    __syncthreads();
#pragma unroll
    for (int st = 128; st > 0; st >>= 1) {
        if (tid < st) sdot[tid] += sdot[tid + st];
        __syncthreads();
    }
    if (tid == 0) {
        float s = (float)sdot[0] + score_b[0];
        float kf = 1.0f / (1.0f + expf(-s));            // fp32 sigmoid, like ref
        int k = (int)(kf * (float)RR);                   // fp32 mul + trunc, like ref
        if (k < 1) k = 1;
        if (k > RR) k = RR;
        sh_k = k;
        d_cnt[b] = 0;                                   // reset for next replay
    }
    __syncthreads();

    // (b) radix select k-th largest among d_mags[b*RR .. +RR)
    //     (monotone float bits; __ldcg for cross-SM visibility within launch)
    unsigned prefix = 0;
    int k = sh_k;
    const float* mags = d_mags + b * RR;

    for (int shift = 24; shift >= 0; shift -= 8) {
        hist[tid] = 0;
        __syncthreads();
        unsigned hi_mask = (shift == 24) ? 0u : (0xFFFFFFFFu << (shift + 8));
#pragma unroll
        for (int i = 0; i < RR / 256; i++) {            // 16 values per thread
            unsigned key = __float_as_uint(__ldcg(&mags[tid + i * 256]));
            unsigned digit = ((key & hi_mask) == (prefix & hi_mask))
                                 ? ((key >> shift) & 0xFFu) : 256u;
            unsigned peers = __match_any_sync(0xffffffffu, digit);
            int leader = __ffs(peers) - 1;
            if (lane == leader && digit < 256u)
                atomicAdd(&hist[digit], (unsigned)__popc(peers));
        }
        __syncthreads();

        // parallel suffix sum: suf[d] = sum_{j >= d} hist[j]
        sufA[tid] = hist[tid];
        __syncthreads();
        unsigned* src = sufA;
        unsigned* dst = sufB;
#pragma unroll
        for (int off = 1; off < 256; off <<= 1) {
            unsigned add = (tid + off < 256) ? src[tid + off] : 0u;
            dst[tid] = src[tid] + add;
            __syncthreads();
            unsigned* t = src; src = dst; dst = t;
        }
        unsigned mycum  = src[tid];
        unsigned nextcum = (tid == 255) ? 0u : src[tid + 1];
        if (mycum >= (unsigned)k && nextcum < (unsigned)k) {
            sh_prefix = prefix | ((unsigned)tid << shift);
            sh_k = k - (int)nextcum;
        }
        __syncthreads();
        prefix = sh_prefix;
        k = sh_k;
        __syncthreads();
    }

    if (tid == 0) d_thr[b] = __uint_as_float(prefix);
}

// ---------------------------------------------------------------------------
// Kernel 2: write-only zeroing of dropped rows (exact R8 form — the fastest
// measured variant). Kept rows exit immediately; dropped rows emit 4KB of
// full-sector zero stores. Traffic ~= drop_fraction * 134MB.
// ---------------------------------------------------------------------------
__global__ void __launch_bounds__(256)
zero_kernel(float4* __restrict__ out) {
    int gwarp = (blockIdx.x * blockDim.x + threadIdx.x) >> 5;
    int lane = threadIdx.x & 31;
    int b = gwarp >> 12;                                // 4096 rows per batch

    if (d_mags[gwarp] >= d_thr[b]) return;              // kept: already final

    float4* orow = out + (size_t)gwarp * 256;
    const float4 z = make_float4(0.f, 0.f, 0.f, 0.f);
#pragma unroll
    for (int i = 0; i < 8; i++)
        orow[lane + i * 32] = z;
}

// ---------------------------------------------------------------------------
extern "C" void kernel_launch(void* const* d_in, const int* in_sizes, int n_in,
                              void* d_out, int out_size) {
    const float* w       = (const float*)d_in[0];  // [8,4096,1024] f32
    const float* logits  = (const float*)d_in[1];  // [8,1024] f32
    const float* score_w = (const float*)d_in[2];  // [1024,1] f32
    const float* score_b = (const float*)d_in[3];  // [1] f32

    (void)in_sizes; (void)n_in; (void)out_size;

    // 32768 rows, 1 warp per row -> 4096 blocks; thresholds overlap the copy
    copy_norms_thr_kernel<<<4096, 256>>>((const float4*)w, (float4*)d_out,
                                         logits, score_w, score_b);
    // zero the dropped rows only
    zero_kernel<<<4096, 256>>>((float4*)d_out);
}

// round 14
// speedup vs baseline: 2.1484x; 1.0170x over previous
#include <cuda_runtime.h>
#include <math.h>

#define BB 8
#define RR 4096
#define CC 1024
#define NROW (BB * RR)
#define NORM_BLKS 4096     // bids [0, 4096): norms + per-batch threshold
#define OUT_BLKS  4096     // bids [4096, 8192): output (copy kept / zero dropped)

// Scratch + sync state (no allocations allowed; zero-init at module load,
// self-reset every run for graph replay).
__device__ float    d_mags[NROW];
__device__ float    d_thr[BB];
__device__ unsigned d_cnt[BB];    // norms-blocks-done counter per batch
__device__ unsigned d_flag[BB];   // thr-ready flag per batch
__device__ unsigned d_ocnt[BB];   // out-blocks-done counter per batch (for reset)

// Branch-free two-sum accumulate: s += t with running compensation c.
__device__ __forceinline__ void twosum_acc(float& s, float& c, float t) {
    float y  = s + t;
    float bp = y - s;
    c += (s - (y - bp)) + (t - bp);
    s = y;
}
__device__ __forceinline__ void twosum_merge(float& s, float& c, float so, float co) {
    float S  = s + so;
    float bp = S - s;
    float e  = (s - (S - bp)) + (so - bp);
    c = c + co + e;
    s = S;
}

// ---------------------------------------------------------------------------
// One launch, two block phases, overlapped by HW block-scheduling order:
//
//  Phase N (bids 0..4095): per-row compensated-fp32 L2 norms of batch
//    b = bid/512 (read-only streaming). The last block of each batch (atomic
//    counter) additionally computes k (fp64 score dot -> fp32 sigmoid ->
//    trunc, matching the jax boundary) and the k-th largest magnitude via
//    4x8-bit radix select, then publishes d_thr[b] + d_flag[b].
//
//  Phase O (bids 4096..8191): for batch b = (bid-4096)/512, spin-wait on
//    d_flag[b] (volatile poll + nanosleep: no LTS atomic contention), then
//    emit output rows: kept -> copy from W, dropped -> zero stores.
//
//  Liveness: N-blocks never wait and always retire; O-blocks have strictly
//  higher bids so the machine fills with N-blocks first => guaranteed
//  progress, no deadlock. Counters/flags self-reset for graph replay.
// ---------------------------------------------------------------------------
__global__ void __launch_bounds__(256)
fused_all_kernel(const float4* __restrict__ w, float4* __restrict__ out,
                 const float* __restrict__ logits,
                 const float* __restrict__ score_w,
                 const float* __restrict__ score_b) {
    const int tid  = threadIdx.x;
    const int lane = tid & 31;
    const int warp = tid >> 5;

    if (blockIdx.x < NORM_BLKS) {
        // =================== Phase N: norms (+ threshold) ===================
        const int gwarp = (blockIdx.x << 3) + warp;       // 8 rows per block
        const int b = blockIdx.x >> 9;                    // 512 blocks per batch

        __shared__ double   sdot[256];
        __shared__ unsigned hist[256], sufA[256], sufB[256];
        __shared__ unsigned sh_prefix, sh_done;
        __shared__ int      sh_k;

        {
            const float4* row = w + (size_t)gwarp * 256;
            float s0 = 0.f, c0 = 0.f, s1 = 0.f, c1 = 0.f;
            float s2 = 0.f, c2 = 0.f, s3 = 0.f, c3 = 0.f;
#pragma unroll
            for (int i = 0; i < 8; i++) {
                float4 v = row[lane + i * 32];
                twosum_acc(s0, c0, v.x * v.x);
                twosum_acc(s1, c1, v.y * v.y);
                twosum_acc(s2, c2, v.z * v.z);
                twosum_acc(s3, c3, v.w * v.w);
            }
            twosum_merge(s0, c0, s1, c1);
            twosum_merge(s2, c2, s3, c3);
            twosum_merge(s0, c0, s2, c2);
#pragma unroll
            for (int off = 16; off > 0; off >>= 1) {
                float so = __shfl_down_sync(0xffffffffu, s0, off);
                float co = __shfl_down_sync(0xffffffffu, c0, off);
                twosum_merge(s0, c0, so, co);
            }
            if (lane == 0) d_mags[gwarp] = sqrtf(s0 + c0);
        }

        __syncthreads();                                  // all 8 d_mags written
        if (tid == 0) {
            __threadfence();                              // publish d_mags
            sh_done = atomicAdd(&d_cnt[b], 1u);
        }
        __syncthreads();
        if (sh_done != 511u) return;                      // not the last block

        // ---- (a) fp64 score dot -> fp32 sigmoid -> k ----
        double acc = 0.0;
        for (int j = tid; j < CC; j += 256)
            acc += (double)logits[b * CC + j] * (double)score_w[j];
        sdot[tid] = acc;
        __syncthreads();
#pragma unroll
        for (int st = 128; st > 0; st >>= 1) {
            if (tid < st) sdot[tid] += sdot[tid + st];
            __syncthreads();
        }
        if (tid == 0) {
            float s = (float)sdot[0] + score_b[0];
            float kf = 1.0f / (1.0f + expf(-s));          // fp32 sigmoid, like ref
            int k = (int)(kf * (float)RR);                 // fp32 mul + trunc, like ref
            if (k < 1) k = 1;
            if (k > RR) k = RR;
            sh_k = k;
            d_cnt[b] = 0;                                 // reset for replay
        }
        __syncthreads();

        // ---- (b) radix select k-th largest among d_mags[b*RR .. +RR) ----
        unsigned prefix = 0;
        int k = sh_k;
        const float* mags = d_mags + b * RR;

        for (int shift = 24; shift >= 0; shift -= 8) {
            hist[tid] = 0;
            __syncthreads();
            unsigned hi_mask = (shift == 24) ? 0u : (0xFFFFFFFFu << (shift + 8));
#pragma unroll
            for (int i = 0; i < RR / 256; i++) {          // 16 values per thread
                unsigned key = __float_as_uint(__ldcg(&mags[tid + i * 256]));
                unsigned digit = ((key & hi_mask) == (prefix & hi_mask))
                                     ? ((key >> shift) & 0xFFu) : 256u;
                unsigned peers = __match_any_sync(0xffffffffu, digit);
                int leader = __ffs(peers) - 1;
                if (lane == leader && digit < 256u)
                    atomicAdd(&hist[digit], (unsigned)__popc(peers));
            }
            __syncthreads();

            sufA[tid] = hist[tid];                        // suffix sum over bins
            __syncthreads();
            unsigned* src = sufA;
            unsigned* dst = sufB;
#pragma unroll
            for (int off = 1; off < 256; off <<= 1) {
                unsigned add = (tid + off < 256) ? src[tid + off] : 0u;
                dst[tid] = src[tid] + add;
                __syncthreads();
                unsigned* t = src; src = dst; dst = t;
            }
            unsigned mycum  = src[tid];
            unsigned nextcum = (tid == 255) ? 0u : src[tid + 1];
            if (mycum >= (unsigned)k && nextcum < (unsigned)k) {
                sh_prefix = prefix | ((unsigned)tid << shift);
                sh_k = k - (int)nextcum;
            }
            __syncthreads();
            prefix = sh_prefix;
            k = sh_k;
            __syncthreads();
        }

        if (tid == 0) {
            d_thr[b] = __uint_as_float(prefix);
            __threadfence();                              // release
            atomicExch(&d_flag[b], 1u);                   // thr ready
        }
    } else {
        // ======================= Phase O: output ===========================
        const int obid = blockIdx.x - NORM_BLKS;
        const int gwarp = (obid << 3) + warp;             // same row mapping
        const int b = obid >> 9;

        __shared__ float sh_thr;

        if (tid == 0) {
            // Volatile poll (plain L2 read), not an atomic RMW: 4096 spinning
            // blocks must not serialize on the LTS atomic unit for 8 addresses
            // while phase N is streaming.
            while (*(volatile unsigned*)&d_flag[b] == 0u)
                __nanosleep(128);
            __threadfence();                              // acquire: order reads
            sh_thr = __ldcg(&d_thr[b]);
        }
        __syncthreads();
        const float thr = sh_thr;

        float4* orow = out + (size_t)gwarp * 256;
        if (__ldcg(&d_mags[gwarp]) >= thr) {
            const float4* row = w + (size_t)gwarp * 256;
#pragma unroll
            for (int i = 0; i < 8; i++)
                orow[lane + i * 32] = row[lane + i * 32]; // kept: copy
        } else {
            const float4 z = make_float4(0.f, 0.f, 0.f, 0.f);
#pragma unroll
            for (int i = 0; i < 8; i++)
                orow[lane + i * 32] = z;                  // dropped: zeros
        }

        __syncthreads();
        if (tid == 0) {                                   // last out block resets
            unsigned old = atomicAdd(&d_ocnt[b], 1u);
            if (old == 511u) {
                d_ocnt[b] = 0;
                atomicExch(&d_flag[b], 0u);               // reset for replay
            }
        }
    }
}

// ---------------------------------------------------------------------------
extern "C" void kernel_launch(void* const* d_in, const int* in_sizes, int n_in,
                              void* d_out, int out_size) {
    const float* w       = (const float*)d_in[0];  // [8,4096,1024] f32
    const float* logits  = (const float*)d_in[1];  // [8,1024] f32
    const float* score_w = (const float*)d_in[2];  // [1024,1] f32
    const float* score_b = (const float*)d_in[3];  // [1] f32

    (void)in_sizes; (void)n_in; (void)out_size;

    fused_all_kernel<<<NORM_BLKS + OUT_BLKS, 256>>>(
        (const float4*)w, (float4*)d_out, logits, score_w, score_b);
}